// round 14
// baseline (speedup 1.0000x reference)
#include <cuda_runtime.h>
#include <cuda_fp16.h>
#include <cstdint>

// ---------------------------------------------------------------------------
// Problem constants
// ---------------------------------------------------------------------------
#define IN_DIM   1024
#define HID      2048
#define OUT_DIM  1000
#define NPAD_OUT 1024
#define BATCH    4096
#define STEPS    30
#define NPI      30
#define EPSN     1e-12f

#define GZ_IN  128
#define GZ_REC 256
#define GZ_OUT 64
#define NBZ (GZ_IN + GZ_REC + GZ_OUT)   // 448
#define GY_IN  32
#define GY_REC 64
#define GY_OUT 64
#define NBY (GY_IN + GY_REC + GY_OUT)   // 160
#define NB_F 148                        // fused-PI grid (co-resident by construction)

// ---------------------------------------------------------------------------
// Device scratch
// ---------------------------------------------------------------------------
__device__ float g_u[6144];
__device__ float g_y[6144];
__device__ float g_partY[3][64];
__device__ float g_partZ[3][256];
__device__ float g_sigpart[3][256];
__device__ float g_inv_sigma[3];
__device__ unsigned g_bar;              // software grid barrier (zeroed each replay)

__device__ uint2 g_xp[(size_t)BATCH * IN_DIM / 2];
__device__ uint2 g_Winp[(size_t)HID * IN_DIM / 2];
__device__ uint2 g_Wrecp[(size_t)HID * HID / 2];
__device__ uint2 g_Woutp[(size_t)NPAD_OUT * HID / 2];
__device__ float g_xraw[(size_t)BATCH * HID];
__device__ uint32_t g_hf0[(size_t)BATCH * HID / 2];
__device__ uint32_t g_hf1[(size_t)BATCH * HID / 2];

// ---------------------------------------------------------------------------
// helpers
// ---------------------------------------------------------------------------
__device__ __forceinline__ uint32_t smem_u32(const void* p) {
    uint32_t a;
    asm("{ .reg .u64 t; cvta.to.shared.u64 t, %1; cvt.u32.u64 %0, t; }" : "=r"(a) : "l"(p));
    return a;
}
#define CP16(dst, src) \
    asm volatile("cp.async.cg.shared.global [%0], [%1], 16;" :: "r"(dst), "l"(src) : "memory")
#define CP_COMMIT() asm volatile("cp.async.commit_group;" ::: "memory")
#define CP_WAIT(n) asm volatile("cp.async.wait_group %0;" :: "n"(n) : "memory")

__device__ __forceinline__ void split2_bf(float x0, float x1, uint32_t& hi, uint32_t& lo) {
    uint32_t h;
    asm("cvt.rn.bf16x2.f32 %0, %1, %2;" : "=r"(h) : "f"(x1), "f"(x0));
    float h0 = __uint_as_float(h << 16);
    float h1 = __uint_as_float(h & 0xffff0000u);
    float r0 = x0 - h0, r1 = x1 - h1;
    uint32_t l;
    asm("cvt.rn.bf16x2.f32 %0, %1, %2;" : "=r"(l) : "f"(r1), "f"(r0));
    hi = h; lo = l;
}

__device__ __forceinline__ void split2_hf(float x0, float x1, uint32_t& hi, uint32_t& lo) {
    __half a = __float2half_rn(x0), b = __float2half_rn(x1);
    __half2 hh = __halves2half2(a, b);
    float r0 = x0 - __half2float(a), r1 = x1 - __half2float(b);
    __half2 ll = __halves2half2(__float2half_rn(r0), __float2half_rn(r1));
    hi = *(uint32_t*)&hh; lo = *(uint32_t*)&ll;
}

__device__ __forceinline__ uint32_t pack_hf(float x0, float x1) {
    __half2 hh = __halves2half2(__float2half_rn(x0), __float2half_rn(x1));
    return *(uint32_t*)&hh;
}

// ---------------------------------------------------------------------------
// Prepack kernels
// ---------------------------------------------------------------------------
__global__ void prepack_bf(const float* __restrict__ src, uint2* __restrict__ dst, int n4) {
    int i = blockIdx.x * 256 + threadIdx.x;
    if (i < n4) {
        float4 v = ((const float4*)src)[i];
        uint32_t h01, l01, h23, l23;
        split2_bf(v.x, v.y, h01, l01);
        split2_bf(v.z, v.w, h23, l23);
        ((uint4*)dst)[i] = make_uint4(h01, l01, h23, l23);
    }
}

__global__ void prepack_hf(const float* __restrict__ src, uint2* __restrict__ dst, int n4) {
    int i = blockIdx.x * 256 + threadIdx.x;
    if (i < n4) {
        float4 v = ((const float4*)src)[i];
        uint32_t h01, l01, h23, l23;
        split2_hf(v.x, v.y, h01, l01);
        split2_hf(v.z, v.w, h23, l23);
        ((uint4*)dst)[i] = make_uint4(h01, l01, h23, l23);
    }
}

__global__ void prepack_hf_pad(const float* __restrict__ src, uint2* __restrict__ dst,
                               int src_rows, int K4, int n4) {
    int i = blockIdx.x * 256 + threadIdx.x;
    if (i < n4) {
        int row = i / K4;
        uint4 o = make_uint4(0u, 0u, 0u, 0u);
        if (row < src_rows) {
            float4 v = ((const float4*)src)[i];
            uint32_t h01, l01, h23, l23;
            split2_hf(v.x, v.y, h01, l01);
            split2_hf(v.z, v.w, h23, l23);
            o = make_uint4(h01, l01, h23, l23);
        }
        ((uint4*)dst)[i] = o;
    }
}

// ---------------------------------------------------------------------------
// Power iteration (fp32, reference-exact sequence), fused: 148 blocks, unit loops
// ---------------------------------------------------------------------------
struct PiCtx { int m, bg, G, M, N; const float* W; float* ubuf; float* ybuf; };

__device__ __forceinline__ PiCtx pi_ctxZ(int b, const float* Win, const float* Wrec,
                                         const float* Wout) {
    PiCtx c;
    if (b < GZ_IN) {
        c.m = 0; c.bg = b; c.G = GZ_IN; c.M = HID; c.N = IN_DIM;
        c.W = Win; c.ubuf = g_u; c.ybuf = g_y;
    } else if (b < GZ_IN + GZ_REC) {
        c.m = 1; c.bg = b - GZ_IN; c.G = GZ_REC; c.M = HID; c.N = HID;
        c.W = Wrec; c.ubuf = g_u + 2048; c.ybuf = g_y + 2048;
    } else {
        c.m = 2; c.bg = b - GZ_IN - GZ_REC; c.G = GZ_OUT; c.M = OUT_DIM; c.N = HID;
        c.W = Wout; c.ubuf = g_u + 4096; c.ybuf = g_y + 4096;
    }
    return c;
}

__device__ __forceinline__ PiCtx pi_ctxY(int b, const float* Win, const float* Wrec,
                                         const float* Wout) {
    PiCtx c;
    if (b < GY_IN) {
        c.m = 0; c.bg = b; c.G = GY_IN; c.M = HID; c.N = IN_DIM;
        c.W = Win; c.ubuf = g_u; c.ybuf = g_y;
    } else if (b < GY_IN + GY_REC) {
        c.m = 1; c.bg = b - GY_IN; c.G = GY_REC; c.M = HID; c.N = HID;
        c.W = Wrec; c.ubuf = g_u + 2048; c.ybuf = g_y + 2048;
    } else {
        c.m = 2; c.bg = b - GY_IN - GY_REC; c.G = GY_OUT; c.M = OUT_DIM; c.N = HID;
        c.W = Wout; c.ubuf = g_u + 4096; c.ybuf = g_y + 4096;
    }
    return c;
}

__device__ __forceinline__ float block_sum_partials(const float* part, int G, float* red) {
    int t = threadIdx.x;
    red[t] = (t < G) ? part[t] : 0.0f;
    __syncthreads();
#pragma unroll
    for (int s = 128; s > 0; s >>= 1) {
        if (t < s) red[t] += red[t + s];
        __syncthreads();
    }
    float v = red[0];
    __syncthreads();
    return v;
}

__global__ void pi_init() {
    int t = threadIdx.x;
    for (int i = t; i < 2048; i += 256) {
        g_u[i] = 1.0f;
        g_u[2048 + i] = 1.0f;
        if (i < OUT_DIM) g_u[4096 + i] = 1.0f;
    }
    for (int g = t; g < 256; g += 256) {
        g_partZ[0][g] = 0.0f; g_partZ[1][g] = 0.0f; g_partZ[2][g] = 0.0f;
    }
    if (t == 0) {
        g_partZ[0][0] = (float)HID;
        g_partZ[1][0] = (float)HID;
        g_partZ[2][0] = (float)OUT_DIM;
        g_bar = 0u;
    }
}

// Unit bodies — identical math to the proven multi-launch kernels, unit-indexed.
__device__ void phaseY_unit(int u, const float* Win, const float* Wrec, const float* Wout,
                            float* red, float* ssq) {
    PiCtx c = pi_ctxY(u, Win, Wrec, Wout);
    int gz = (c.m == 1) ? GZ_REC : ((c.m == 0) ? GZ_IN : GZ_OUT);
    float ss = block_sum_partials(g_partZ[c.m], gz, red);
    float su = 1.0f / (sqrtf(ss) + EPSN);

    int cl = threadIdx.x & 31;
    int seg = threadIdx.x >> 5;
    int col = c.bg * 32 + cl;
    int rps = (c.M + 7) / 8;
    int r0 = seg * rps;
    int iend = min(r0 + rps, c.M);

    const float* Wc = c.W + col;
    float a0=0.f,a1=0.f,a2=0.f,a3=0.f,a4=0.f,a5=0.f,a6=0.f,a7=0.f;
    int i = r0;
    for (; i + 7 < iend; i += 8) {
        a0 += Wc[(size_t)(i+0)*c.N] * c.ubuf[i+0];
        a1 += Wc[(size_t)(i+1)*c.N] * c.ubuf[i+1];
        a2 += Wc[(size_t)(i+2)*c.N] * c.ubuf[i+2];
        a3 += Wc[(size_t)(i+3)*c.N] * c.ubuf[i+3];
        a4 += Wc[(size_t)(i+4)*c.N] * c.ubuf[i+4];
        a5 += Wc[(size_t)(i+5)*c.N] * c.ubuf[i+5];
        a6 += Wc[(size_t)(i+6)*c.N] * c.ubuf[i+6];
        a7 += Wc[(size_t)(i+7)*c.N] * c.ubuf[i+7];
    }
    for (; i < iend; ++i) a0 += Wc[(size_t)i*c.N] * c.ubuf[i];
    float acc = ((a0+a1)+(a2+a3)) + ((a4+a5)+(a6+a7));

    red[threadIdx.x] = acc;
    __syncthreads();
    if (seg == 0) {
        float tot = 0.0f;
        for (int s = 0; s < 8; ++s) tot += red[cl + s * 32];
        float yv = tot * su;
        c.ybuf[col] = yv;
        ssq[cl] = yv * yv;
    }
    __syncthreads();
    if (threadIdx.x == 0) {
        float p = 0.0f;
        for (int q = 0; q < 32; ++q) p += ssq[q];
        g_partY[c.m][c.bg] = p;
    }
    __syncthreads();
}

__device__ void phaseZ_unit(int u, const float* Win, const float* Wrec, const float* Wout,
                            float* red, float* wsq) {
    PiCtx c = pi_ctxZ(u, Win, Wrec, Wout);
    int gy = (c.m == 1) ? GY_REC : ((c.m == 0) ? GY_IN : GY_OUT);
    float ss = block_sum_partials(g_partY[c.m], gy, red);
    float sv = 1.0f / (sqrtf(ss) + EPSN);

    int warp = threadIdx.x >> 5, lane = threadIdx.x & 31;
    int rpb = (c.M + c.G - 1) / c.G;
    int rend = min(c.bg * rpb + rpb, c.M);

    float acc2 = 0.0f;
    for (int r = c.bg * rpb + warp; r < rend; r += 8) {
        const float* row = c.W + (size_t)r * c.N;
        float a0=0.f,a1=0.f,a2=0.f,a3=0.f,a4=0.f,a5=0.f,a6=0.f,a7=0.f;
        for (int j = lane; j < c.N; j += 256) {
            a0 += row[j      ] * c.ybuf[j      ];
            a1 += row[j +  32] * c.ybuf[j +  32];
            a2 += row[j +  64] * c.ybuf[j +  64];
            a3 += row[j +  96] * c.ybuf[j +  96];
            a4 += row[j + 128] * c.ybuf[j + 128];
            a5 += row[j + 160] * c.ybuf[j + 160];
            a6 += row[j + 192] * c.ybuf[j + 192];
            a7 += row[j + 224] * c.ybuf[j + 224];
        }
        float a = ((a0+a1)+(a2+a3)) + ((a4+a5)+(a6+a7));
        for (int o = 16; o; o >>= 1) a += __shfl_down_sync(0xffffffffu, a, o);
        if (lane == 0) {
            float z = a * sv;
            c.ubuf[r] = z;
            acc2 += z * z;
        }
    }
    if (lane == 0) wsq[warp] = acc2;
    __syncthreads();
    if (threadIdx.x == 0) {
        float p = 0.0f;
        for (int w = 0; w < 8; ++w) p += wsq[w];
        g_partZ[c.m][c.bg] = p;
    }
    __syncthreads();
}

__device__ void sigma_unit(int u, const float* Win, const float* Wrec, const float* Wout,
                           float* red, float* wsq) {
    PiCtx c = pi_ctxZ(u, Win, Wrec, Wout);
    int gy = (c.m == 1) ? GY_REC : ((c.m == 0) ? GY_IN : GY_OUT);
    float ssz = block_sum_partials(g_partZ[c.m], c.G, red);
    float ssy = block_sum_partials(g_partY[c.m], gy, red);
    float su = 1.0f / (sqrtf(ssz) + EPSN);
    float sv = 1.0f / (sqrtf(ssy) + EPSN);

    int warp = threadIdx.x >> 5, lane = threadIdx.x & 31;
    int rpb = (c.M + c.G - 1) / c.G;
    int rend = min(c.bg * rpb + rpb, c.M);

    float contrib = 0.0f;
    for (int r = c.bg * rpb + warp; r < rend; r += 8) {
        const float* row = c.W + (size_t)r * c.N;
        float a0=0.f,a1=0.f,a2=0.f,a3=0.f,a4=0.f,a5=0.f,a6=0.f,a7=0.f;
        for (int j = lane; j < c.N; j += 256) {
            a0 += row[j      ] * c.ybuf[j      ];
            a1 += row[j +  32] * c.ybuf[j +  32];
            a2 += row[j +  64] * c.ybuf[j +  64];
            a3 += row[j +  96] * c.ybuf[j +  96];
            a4 += row[j + 128] * c.ybuf[j + 128];
            a5 += row[j + 160] * c.ybuf[j + 160];
            a6 += row[j + 192] * c.ybuf[j + 192];
            a7 += row[j + 224] * c.ybuf[j + 224];
        }
        float a = ((a0+a1)+(a2+a3)) + ((a4+a5)+(a6+a7));
        for (int o = 16; o; o >>= 1) a += __shfl_down_sync(0xffffffffu, a, o);
        if (lane == 0) contrib += (su * c.ubuf[r]) * (sv * a);
    }
    if (lane == 0) wsq[warp] = contrib;
    __syncthreads();
    if (threadIdx.x == 0) {
        float p = 0.0f;
        for (int w = 0; w < 8; ++w) p += wsq[w];
        g_sigpart[c.m][c.bg] = p;
    }
    __syncthreads();
}

// Grid barrier: release-arrive (fence + atomicAdd), acquire-spin. 148 blocks
// are always co-resident (tiny smem/regs, 256 thr) -> cannot deadlock.
__device__ __forceinline__ void grid_barrier(unsigned target) {
    __syncthreads();
    if (threadIdx.x == 0) {
        __threadfence();
        atomicAdd(&g_bar, 1u);
        unsigned v;
        do {
            asm volatile("ld.acquire.gpu.u32 %0, [%1];" : "=r"(v) : "l"(&g_bar) : "memory");
        } while (v < target);
    }
    __syncthreads();
}

__global__ __launch_bounds__(256)
void pi_fused(const float* __restrict__ Win, const float* __restrict__ Wrec,
              const float* __restrict__ Wout) {
    __shared__ float red[256];
    __shared__ float ssq[32];
    __shared__ float wsq[8];
    unsigned nb = 0;
    for (int it = 0; it < NPI; ++it) {
        for (int u = blockIdx.x; u < NBY; u += NB_F)
            phaseY_unit(u, Win, Wrec, Wout, red, ssq);
        grid_barrier(++nb * NB_F);
        for (int u = blockIdx.x; u < NBZ; u += NB_F)
            phaseZ_unit(u, Win, Wrec, Wout, red, wsq);
        grid_barrier(++nb * NB_F);
    }
    for (int u = blockIdx.x; u < NBY; u += NB_F)      // final v = norm(W^T u)
        phaseY_unit(u, Win, Wrec, Wout, red, ssq);
    grid_barrier(++nb * NB_F);
    for (int u = blockIdx.x; u < NBZ; u += NB_F)      // sigma partials
        sigma_unit(u, Win, Wrec, Wout, red, wsq);
    grid_barrier(++nb * NB_F);
    if (blockIdx.x == 0 && threadIdx.x < 3) {
        int m = threadIdx.x;
        int G = (m == 1) ? GZ_REC : ((m == 0) ? GZ_IN : GZ_OUT);
        float s = 0.0f;
        for (int g = 0; g < G; ++g) s += g_sigpart[m][g];
        g_inv_sigma[m] = 1.0f / s;
    }
}

// ---------------------------------------------------------------------------
// MMA wrappers
// ---------------------------------------------------------------------------
__device__ __forceinline__ void mma_bf(float* c, uint32_t a0, uint32_t a1, uint32_t a2,
                                       uint32_t a3, uint32_t b0, uint32_t b1) {
    asm volatile(
        "mma.sync.aligned.m16n8k16.row.col.f32.bf16.bf16.f32 "
        "{%0,%1,%2,%3}, {%4,%5,%6,%7}, {%8,%9}, {%0,%1,%2,%3};"
        : "+f"(c[0]), "+f"(c[1]), "+f"(c[2]), "+f"(c[3])
        : "r"(a0), "r"(a1), "r"(a2), "r"(a3), "r"(b0), "r"(b1));
}
__device__ __forceinline__ void mma_hf(float* c, uint32_t a0, uint32_t a1, uint32_t a2,
                                       uint32_t a3, uint32_t b0, uint32_t b1) {
    asm volatile(
        "mma.sync.aligned.m16n8k16.row.col.f32.f16.f16.f32 "
        "{%0,%1,%2,%3}, {%4,%5,%6,%7}, {%8,%9}, {%0,%1,%2,%3};"
        : "+f"(c[0]), "+f"(c[1]), "+f"(c[2]), "+f"(c[3])
        : "r"(a0), "r"(a1), "r"(a2), "r"(a3), "r"(b0), "r"(b1));
}

#define BM 128
#define BN 128
#define BKT 32
#define PSTRIDE 20     // uint2 per packed-pair row (160B)
#define ASTRIDE 80     // bytes per fp16 A row (64 data + 16 pad)
#define A_ST_BYTES 10240
#define B_ST_BYTES 20480
#define H2_SMEM (2 * A_ST_BYTES + 2 * B_ST_BYTES)   // 61440

// ---------------------------------------------------------------------------
// 3-term bf16 GEMM on packed pairs (xproj only)
// ---------------------------------------------------------------------------
__global__ __launch_bounds__(256)
void gemm_bf3(const uint2* __restrict__ A, const uint2* __restrict__ B,
              float* __restrict__ Cf, int N, int K) {
    __shared__ __align__(16) uint2 As[BM * PSTRIDE];
    __shared__ __align__(16) uint2 Bs[BN * PSTRIDE];

    int tid = threadIdx.x;
    int bm = blockIdx.y * BM, bn = blockIdx.x * BN;
    int Kp = K >> 1;

    int rowq[4], uq[4];
#pragma unroll
    for (int q = 0; q < 4; ++q) {
        int idx = tid + q * 256;
        rowq[q] = idx >> 3;
        uq[q] = (idx & 7) * 2;
    }

    int warp = tid >> 5, lane = tid & 31;
    int wm = (warp & 1) * 64;
    int wn = (warp >> 1) * 32;
    int g = lane >> 2;
    int t = lane & 3;

    float acc[4][4][4];
#pragma unroll
    for (int i = 0; i < 4; ++i)
#pragma unroll
        for (int j = 0; j < 4; ++j)
#pragma unroll
            for (int q = 0; q < 4; ++q) acc[i][j][q] = 0.0f;

    uint4 pa[4], pb[4];
#pragma unroll
    for (int q = 0; q < 4; ++q) {
        pa[q] = *(const uint4*)(A + (size_t)(bm + rowq[q]) * Kp + uq[q]);
        pb[q] = *(const uint4*)(B + (size_t)(bn + rowq[q]) * Kp + uq[q]);
    }

    int KT = K / BKT;
    for (int kt = 0; kt < KT; ++kt) {
        __syncthreads();
#pragma unroll
        for (int q = 0; q < 4; ++q) {
            *(uint4*)&As[rowq[q] * PSTRIDE + uq[q]] = pa[q];
            *(uint4*)&Bs[rowq[q] * PSTRIDE + uq[q]] = pb[q];
        }
        __syncthreads();

        if (kt + 1 < KT) {
            int off = (kt + 1) * 16;
#pragma unroll
            for (int q = 0; q < 4; ++q) {
                pa[q] = *(const uint4*)(A + (size_t)(bm + rowq[q]) * Kp + off + uq[q]);
                pb[q] = *(const uint4*)(B + (size_t)(bn + rowq[q]) * Kp + off + uq[q]);
            }
        }

#pragma unroll
        for (int kp = 0; kp < 16; kp += 8) {
            uint2 Af[4][4];
            uint2 Bf[4][2];
#pragma unroll
            for (int mf = 0; mf < 4; ++mf) {
                int rb = wm + mf * 16 + g;
                Af[mf][0] = As[rb * PSTRIDE + kp + t];
                Af[mf][1] = As[(rb + 8) * PSTRIDE + kp + t];
                Af[mf][2] = As[rb * PSTRIDE + kp + t + 4];
                Af[mf][3] = As[(rb + 8) * PSTRIDE + kp + t + 4];
            }
#pragma unroll
            for (int nf = 0; nf < 4; ++nf) {
                int cb = wn + nf * 8 + g;
                Bf[nf][0] = Bs[cb * PSTRIDE + kp + t];
                Bf[nf][1] = Bs[cb * PSTRIDE + kp + t + 4];
            }
#pragma unroll
            for (int nf = 0; nf < 4; ++nf)
#pragma unroll
                for (int mf = 0; mf < 4; ++mf)
                    mma_bf(acc[mf][nf], Af[mf][0].x, Af[mf][1].x, Af[mf][2].x, Af[mf][3].x,
                           Bf[nf][0].x, Bf[nf][1].x);
#pragma unroll
            for (int nf = 0; nf < 4; ++nf)
#pragma unroll
                for (int mf = 0; mf < 4; ++mf)
                    mma_bf(acc[mf][nf], Af[mf][0].x, Af[mf][1].x, Af[mf][2].x, Af[mf][3].x,
                           Bf[nf][0].y, Bf[nf][1].y);
#pragma unroll
            for (int nf = 0; nf < 4; ++nf)
#pragma unroll
                for (int mf = 0; mf < 4; ++mf)
                    mma_bf(acc[mf][nf], Af[mf][0].y, Af[mf][1].y, Af[mf][2].y, Af[mf][3].y,
                           Bf[nf][0].x, Bf[nf][1].x);
        }
    }

#pragma unroll
    for (int mf = 0; mf < 4; ++mf) {
        int r0 = bm + wm + mf * 16 + g;
#pragma unroll
        for (int nf = 0; nf < 4; ++nf) {
            int c0 = bn + wn + nf * 8 + 2 * t;
            float* a = acc[mf][nf];
#pragma unroll
            for (int half = 0; half < 2; ++half) {
                int rr = r0 + half * 8;
                float2 o; o.x = a[half * 2 + 0]; o.y = a[half * 2 + 1];
                *(float2*)(Cf + (size_t)rr * N + c0) = o;
            }
        }
    }
}

// ---------------------------------------------------------------------------
// 2-term fp16 GEMM with cp.async 2-stage pipeline, 2 CTAs/SM.
// ---------------------------------------------------------------------------
template <int OKIND>
__global__ __launch_bounds__(256, 2)
void gemm_h2(const uint32_t* __restrict__ Ah, const uint2* __restrict__ B,
             const float* __restrict__ bias, const float* __restrict__ bias2,
             const float* __restrict__ raw, float* __restrict__ Cf,
             uint32_t* __restrict__ Cp, int N, int Nreal, int K) {
    extern __shared__ __align__(16) uint8_t dynsmem[];
    uint32_t sbase = smem_u32(dynsmem);
    const uint32_t aoff[2] = { 0u, A_ST_BYTES };
    const uint32_t boff[2] = { 2u * A_ST_BYTES, 2u * A_ST_BYTES + B_ST_BYTES };

    int tid = threadIdx.x;
    int bm = blockIdx.y * BM, bn = blockIdx.x * BN;
    int K8 = K >> 3;
    int Kp = K >> 1;

    int arow[2], aq[2];
#pragma unroll
    for (int q = 0; q < 2; ++q) {
        int idx = tid + q * 256;
        arow[q] = idx >> 2;
        aq[q] = idx & 3;
    }
    int brow[4], buq[4];
#pragma unroll
    for (int q = 0; q < 4; ++q) {
        int idx = tid + q * 256;
        brow[q] = idx >> 3;
        buq[q] = (idx & 7) * 2;
    }

    const uint4* A4 = (const uint4*)Ah;

    auto issue_tile = [&](int kt, int s) {
#pragma unroll
        for (int q = 0; q < 2; ++q)
            CP16(sbase + aoff[s] + arow[q] * ASTRIDE + aq[q] * 16,
                 A4 + (size_t)(bm + arow[q]) * K8 + kt * 4 + aq[q]);
#pragma unroll
        for (int q = 0; q < 4; ++q)
            CP16(sbase + boff[s] + brow[q] * 160 + buq[q] * 8,
                 (const uint4*)(B + (size_t)(bn + brow[q]) * Kp + kt * 16 + buq[q]));
        CP_COMMIT();
    };

    int warp = tid >> 5, lane = tid & 31;
    int wm = (warp & 1) * 64;
    int wn = (warp >> 1) * 32;
    int g = lane >> 2;
    int t = lane & 3;

    float acc[4][4][4];
#pragma unroll
    for (int i = 0; i < 4; ++i)
#pragma unroll
        for (int j = 0; j < 4; ++j)
#pragma unroll
            for (int q = 0; q < 4; ++q) acc[i][j][q] = 0.0f;

    int KT = K / BKT;
    issue_tile(0, 0);
    issue_tile(1, 1);

    for (int kt = 0; kt < KT; ++kt) {
        int s = kt & 1;
        if (kt + 1 < KT) { CP_WAIT(1); } else { CP_WAIT(0); }
        __syncthreads();

        const uint8_t* AsB = dynsmem + aoff[s];
        const uint2* Bs = (const uint2*)(dynsmem + boff[s]);
#pragma unroll
        for (int kh = 0; kh < 2; ++kh) {
            uint32_t Af[4][4];
#pragma unroll
            for (int mf = 0; mf < 4; ++mf) {
                int rb = wm + mf * 16 + g;
                const uint8_t* base = AsB + rb * ASTRIDE + kh * 32 + t * 4;
                Af[mf][0] = *(const uint32_t*)(base);
                Af[mf][1] = *(const uint32_t*)(base + 8 * ASTRIDE);
                Af[mf][2] = *(const uint32_t*)(base + 16);
                Af[mf][3] = *(const uint32_t*)(base + 8 * ASTRIDE + 16);
            }
            uint2 Bf[4][2];
            int kp = kh * 8;
#pragma unroll
            for (int nf = 0; nf < 4; ++nf) {
                int cb = wn + nf * 8 + g;
                Bf[nf][0] = Bs[cb * PSTRIDE + kp + t];
                Bf[nf][1] = Bs[cb * PSTRIDE + kp + t + 4];
            }
#pragma unroll
            for (int nf = 0; nf < 4; ++nf)
#pragma unroll
                for (int mf = 0; mf < 4; ++mf)
                    mma_hf(acc[mf][nf], Af[mf][0], Af[mf][1], Af[mf][2], Af[mf][3],
                           Bf[nf][0].x, Bf[nf][1].x);
#pragma unroll
            for (int nf = 0; nf < 4; ++nf)
#pragma unroll
                for (int mf = 0; mf < 4; ++mf)
                    mma_hf(acc[mf][nf], Af[mf][0], Af[mf][1], Af[mf][2], Af[mf][3],
                           Bf[nf][0].y, Bf[nf][1].y);
        }
        __syncthreads();
        if (kt + 2 < KT) issue_tile(kt + 2, s);
    }

    // ---- epilogue ----
    float s_main = (OKIND == 1) ? g_inv_sigma[1] : g_inv_sigma[2];
    float s_in = (OKIND == 1) ? g_inv_sigma[0] : 0.0f;
#pragma unroll
    for (int mf = 0; mf < 4; ++mf) {
        int r0 = bm + wm + mf * 16 + g;
#pragma unroll
        for (int nf = 0; nf < 4; ++nf) {
            int c0 = bn + wn + nf * 8 + 2 * t;
            float* a = acc[mf][nf];
#pragma unroll
            for (int half = 0; half < 2; ++half) {
                int rr = r0 + half * 8;
                float v0 = a[half * 2 + 0];
                float v1 = a[half * 2 + 1];
                if (OKIND == 1) {
                    size_t base = (size_t)rr * N + c0;
                    float2 rw = *(const float2*)(raw + base);
                    v0 = tanhf(v0 * s_main + bias[c0] + rw.x * s_in + bias2[c0]);
                    v1 = tanhf(v1 * s_main + bias[c0 + 1] + rw.y * s_in + bias2[c0 + 1]);
                    Cp[base >> 1] = pack_hf(v0, v1);
                } else {
                    size_t base = (size_t)rr * Nreal;
                    if (c0 < Nreal)     Cf[base + c0]     = v0 * s_main + bias[c0];
                    if (c0 + 1 < Nreal) Cf[base + c0 + 1] = v1 * s_main + bias[c0 + 1];
                }
            }
        }
    }
}

// Step 1 (h0 = 0): h = fp16( tanh(raw*s_in + b_in + b_rec) )
__global__ void step1_kernel(const float* __restrict__ xpraw, const float* __restrict__ bin,
                             const float* __restrict__ brec, uint32_t* __restrict__ hp) {
    size_t i = ((size_t)blockIdx.x * blockDim.x + threadIdx.x) * 4;
    float s_in = g_inv_sigma[0];
    float4 v = *(const float4*)(xpraw + i);
    int col = (int)(i & (HID - 1));
    v.x = tanhf(v.x * s_in + bin[col + 0] + brec[col + 0]);
    v.y = tanhf(v.y * s_in + bin[col + 1] + brec[col + 1]);
    v.z = tanhf(v.z * s_in + bin[col + 2] + brec[col + 2]);
    v.w = tanhf(v.w * s_in + bin[col + 3] + brec[col + 3]);
    uint2 o;
    o.x = pack_hf(v.x, v.y);
    o.y = pack_hf(v.z, v.w);
    *(uint2*)(hp + (i >> 1)) = o;
}

// ---------------------------------------------------------------------------
// Launch
// ---------------------------------------------------------------------------
extern "C" void kernel_launch(void* const* d_in, const int* in_sizes, int n_in,
                              void* d_out, int out_size) {
    (void)in_sizes; (void)n_in; (void)out_size;
    const float* x    = (const float*)d_in[0];
    const float* Win  = (const float*)d_in[1];
    const float* bin  = (const float*)d_in[2];
    const float* Wrec = (const float*)d_in[3];
    const float* brec = (const float*)d_in[4];
    const float* Wout = (const float*)d_in[5];
    const float* bout = (const float*)d_in[6];
    float* out = (float*)d_out;

    uint2 *xp, *winp, *wrecp, *woutp;
    uint32_t *hf0, *hf1;
    float* xraw;
    cudaGetSymbolAddress((void**)&xp, g_xp);
    cudaGetSymbolAddress((void**)&winp, g_Winp);
    cudaGetSymbolAddress((void**)&wrecp, g_Wrecp);
    cudaGetSymbolAddress((void**)&woutp, g_Woutp);
    cudaGetSymbolAddress((void**)&xraw, g_xraw);
    cudaGetSymbolAddress((void**)&hf0, g_hf0);
    cudaGetSymbolAddress((void**)&hf1, g_hf1);

    cudaFuncSetAttribute(gemm_h2<1>, cudaFuncAttributeMaxDynamicSharedMemorySize, H2_SMEM);
    cudaFuncSetAttribute(gemm_h2<2>, cudaFuncAttributeMaxDynamicSharedMemorySize, H2_SMEM);

    pi_init<<<1, 256>>>();
    prepack_bf<<<(BATCH * IN_DIM / 4) / 256, 256>>>(x, xp, BATCH * IN_DIM / 4);
    prepack_bf<<<(HID * IN_DIM / 4) / 256, 256>>>(Win, winp, HID * IN_DIM / 4);
    prepack_hf<<<(HID * HID / 4) / 256, 256>>>(Wrec, wrecp, HID * HID / 4);
    prepack_hf_pad<<<(NPAD_OUT * HID / 4) / 256, 256>>>(Wout, woutp, OUT_DIM, HID / 4,
                                                        NPAD_OUT * HID / 4);
    // raw xproj GEMM (3-term bf16, sigma-independent)
    gemm_bf3<<<dim3(HID / BN, BATCH / BM), 256>>>(xp, winp, xraw, HID, IN_DIM);

    // fused power iteration: 62 launches -> 1 (148 co-resident blocks)
    pi_fused<<<NB_F, 256>>>(Win, Wrec, Wout);

    // step 1
    step1_kernel<<<(BATCH * HID) / (256 * 4), 256>>>(xraw, bin, brec, hf0);

    // steps 2..30 (2-term fp16, cp.async pipeline)
    uint32_t* hin = hf0;
    uint32_t* hout = hf1;
    for (int s = 1; s < STEPS; ++s) {
        gemm_h2<1><<<dim3(HID / BN, BATCH / BM), 256, H2_SMEM>>>(
            hin, wrecp, brec, bin, xraw, nullptr, hout, HID, HID, HID);
        uint32_t* tmp = hin; hin = hout; hout = tmp;
    }

    // out GEMM
    gemm_h2<2><<<dim3(NPAD_OUT / BN, BATCH / BM), 256, H2_SMEM>>>(
        hin, woutp, bout, nullptr, nullptr, out, nullptr, NPAD_OUT, OUT_DIM, HID);
}

// round 15
// speedup vs baseline: 1.0828x; 1.0828x over previous
#include <cuda_runtime.h>
#include <cuda_fp16.h>
#include <cstdint>

// ---------------------------------------------------------------------------
// Problem constants
// ---------------------------------------------------------------------------
#define IN_DIM   1024
#define HID      2048
#define OUT_DIM  1000
#define NPAD_OUT 1024
#define BATCH    4096
#define STEPS    30
#define NPI      30
#define EPSN     1e-12f

#define GZ_IN  128
#define GZ_REC 256
#define GZ_OUT 64
#define NBZ (GZ_IN + GZ_REC + GZ_OUT)   // 448
#define GY_IN  32
#define GY_REC 64
#define GY_OUT 64
#define NBY (GY_IN + GY_REC + GY_OUT)   // 160
#define NB_F 296                        // fused-PI grid: 2 blocks/SM x 148 SMs,
                                        // residency guaranteed (regs capped 128,
                                        // 512 thr/SM, ~1.2KB smem) -> no deadlock

// ---------------------------------------------------------------------------
// Device scratch
// ---------------------------------------------------------------------------
__device__ float g_u[6144];
__device__ float g_y[6144];
__device__ float g_partY[3][64];
__device__ float g_partZ[3][256];
__device__ float g_sigpart[3][256];
__device__ float g_inv_sigma[3];
__device__ unsigned g_bar;              // software grid barrier (zeroed each replay)

__device__ uint2 g_xp[(size_t)BATCH * IN_DIM / 2];
__device__ uint2 g_Winp[(size_t)HID * IN_DIM / 2];
__device__ uint2 g_Wrecp[(size_t)HID * HID / 2];
__device__ uint2 g_Woutp[(size_t)NPAD_OUT * HID / 2];
__device__ float g_xraw[(size_t)BATCH * HID];
__device__ uint32_t g_hf0[(size_t)BATCH * HID / 2];
__device__ uint32_t g_hf1[(size_t)BATCH * HID / 2];

// ---------------------------------------------------------------------------
// helpers
// ---------------------------------------------------------------------------
__device__ __forceinline__ uint32_t smem_u32(const void* p) {
    uint32_t a;
    asm("{ .reg .u64 t; cvta.to.shared.u64 t, %1; cvt.u32.u64 %0, t; }" : "=r"(a) : "l"(p));
    return a;
}
#define CP16(dst, src) \
    asm volatile("cp.async.cg.shared.global [%0], [%1], 16;" :: "r"(dst), "l"(src) : "memory")
#define CP_COMMIT() asm volatile("cp.async.commit_group;" ::: "memory")
#define CP_WAIT(n) asm volatile("cp.async.wait_group %0;" :: "n"(n) : "memory")

__device__ __forceinline__ void split2_bf(float x0, float x1, uint32_t& hi, uint32_t& lo) {
    uint32_t h;
    asm("cvt.rn.bf16x2.f32 %0, %1, %2;" : "=r"(h) : "f"(x1), "f"(x0));
    float h0 = __uint_as_float(h << 16);
    float h1 = __uint_as_float(h & 0xffff0000u);
    float r0 = x0 - h0, r1 = x1 - h1;
    uint32_t l;
    asm("cvt.rn.bf16x2.f32 %0, %1, %2;" : "=r"(l) : "f"(r1), "f"(r0));
    hi = h; lo = l;
}

__device__ __forceinline__ void split2_hf(float x0, float x1, uint32_t& hi, uint32_t& lo) {
    __half a = __float2half_rn(x0), b = __float2half_rn(x1);
    __half2 hh = __halves2half2(a, b);
    float r0 = x0 - __half2float(a), r1 = x1 - __half2float(b);
    __half2 ll = __halves2half2(__float2half_rn(r0), __float2half_rn(r1));
    hi = *(uint32_t*)&hh; lo = *(uint32_t*)&ll;
}

__device__ __forceinline__ uint32_t pack_hf(float x0, float x1) {
    __half2 hh = __halves2half2(__float2half_rn(x0), __float2half_rn(x1));
    return *(uint32_t*)&hh;
}

// ---------------------------------------------------------------------------
// Prepack kernels
// ---------------------------------------------------------------------------
__global__ void prepack_bf(const float* __restrict__ src, uint2* __restrict__ dst, int n4) {
    int i = blockIdx.x * 256 + threadIdx.x;
    if (i < n4) {
        float4 v = ((const float4*)src)[i];
        uint32_t h01, l01, h23, l23;
        split2_bf(v.x, v.y, h01, l01);
        split2_bf(v.z, v.w, h23, l23);
        ((uint4*)dst)[i] = make_uint4(h01, l01, h23, l23);
    }
}

__global__ void prepack_hf(const float* __restrict__ src, uint2* __restrict__ dst, int n4) {
    int i = blockIdx.x * 256 + threadIdx.x;
    if (i < n4) {
        float4 v = ((const float4*)src)[i];
        uint32_t h01, l01, h23, l23;
        split2_hf(v.x, v.y, h01, l01);
        split2_hf(v.z, v.w, h23, l23);
        ((uint4*)dst)[i] = make_uint4(h01, l01, h23, l23);
    }
}

__global__ void prepack_hf_pad(const float* __restrict__ src, uint2* __restrict__ dst,
                               int src_rows, int K4, int n4) {
    int i = blockIdx.x * 256 + threadIdx.x;
    if (i < n4) {
        int row = i / K4;
        uint4 o = make_uint4(0u, 0u, 0u, 0u);
        if (row < src_rows) {
            float4 v = ((const float4*)src)[i];
            uint32_t h01, l01, h23, l23;
            split2_hf(v.x, v.y, h01, l01);
            split2_hf(v.z, v.w, h23, l23);
            o = make_uint4(h01, l01, h23, l23);
        }
        ((uint4*)dst)[i] = o;
    }
}

// ---------------------------------------------------------------------------
// Power iteration (fp32, reference-exact sequence), fused: 296 blocks
// ---------------------------------------------------------------------------
struct PiCtx { int m, bg, G, M, N; const float* W; float* ubuf; float* ybuf; };

__device__ __forceinline__ PiCtx pi_ctxZ(int b, const float* Win, const float* Wrec,
                                         const float* Wout) {
    PiCtx c;
    if (b < GZ_IN) {
        c.m = 0; c.bg = b; c.G = GZ_IN; c.M = HID; c.N = IN_DIM;
        c.W = Win; c.ubuf = g_u; c.ybuf = g_y;
    } else if (b < GZ_IN + GZ_REC) {
        c.m = 1; c.bg = b - GZ_IN; c.G = GZ_REC; c.M = HID; c.N = HID;
        c.W = Wrec; c.ubuf = g_u + 2048; c.ybuf = g_y + 2048;
    } else {
        c.m = 2; c.bg = b - GZ_IN - GZ_REC; c.G = GZ_OUT; c.M = OUT_DIM; c.N = HID;
        c.W = Wout; c.ubuf = g_u + 4096; c.ybuf = g_y + 4096;
    }
    return c;
}

__device__ __forceinline__ PiCtx pi_ctxY(int b, const float* Win, const float* Wrec,
                                         const float* Wout) {
    PiCtx c;
    if (b < GY_IN) {
        c.m = 0; c.bg = b; c.G = GY_IN; c.M = HID; c.N = IN_DIM;
        c.W = Win; c.ubuf = g_u; c.ybuf = g_y;
    } else if (b < GY_IN + GY_REC) {
        c.m = 1; c.bg = b - GY_IN; c.G = GY_REC; c.M = HID; c.N = HID;
        c.W = Wrec; c.ubuf = g_u + 2048; c.ybuf = g_y + 2048;
    } else {
        c.m = 2; c.bg = b - GY_IN - GY_REC; c.G = GY_OUT; c.M = OUT_DIM; c.N = HID;
        c.W = Wout; c.ubuf = g_u + 4096; c.ybuf = g_y + 4096;
    }
    return c;
}

__device__ __forceinline__ float block_sum_partials(const float* part, int G, float* red) {
    int t = threadIdx.x;
    red[t] = (t < G) ? part[t] : 0.0f;
    __syncthreads();
#pragma unroll
    for (int s = 128; s > 0; s >>= 1) {
        if (t < s) red[t] += red[t + s];
        __syncthreads();
    }
    float v = red[0];
    __syncthreads();
    return v;
}

__global__ void pi_init() {
    int t = threadIdx.x;
    for (int i = t; i < 2048; i += 256) {
        g_u[i] = 1.0f;
        g_u[2048 + i] = 1.0f;
        if (i < OUT_DIM) g_u[4096 + i] = 1.0f;
    }
    for (int g = t; g < 256; g += 256) {
        g_partZ[0][g] = 0.0f; g_partZ[1][g] = 0.0f; g_partZ[2][g] = 0.0f;
    }
    if (t == 0) {
        g_partZ[0][0] = (float)HID;
        g_partZ[1][0] = (float)HID;
        g_partZ[2][0] = (float)OUT_DIM;
        g_bar = 0u;
    }
}

// Unit bodies — identical math to the proven multi-launch kernels, unit-indexed.
__device__ void phaseY_unit(int u, const float* Win, const float* Wrec, const float* Wout,
                            float* red, float* ssq) {
    PiCtx c = pi_ctxY(u, Win, Wrec, Wout);
    int gz = (c.m == 1) ? GZ_REC : ((c.m == 0) ? GZ_IN : GZ_OUT);
    float ss = block_sum_partials(g_partZ[c.m], gz, red);
    float su = 1.0f / (sqrtf(ss) + EPSN);

    int cl = threadIdx.x & 31;
    int seg = threadIdx.x >> 5;
    int col = c.bg * 32 + cl;
    int rps = (c.M + 7) / 8;
    int r0 = seg * rps;
    int iend = min(r0 + rps, c.M);

    const float* Wc = c.W + col;
    float a0=0.f,a1=0.f,a2=0.f,a3=0.f,a4=0.f,a5=0.f,a6=0.f,a7=0.f;
    int i = r0;
    for (; i + 7 < iend; i += 8) {
        a0 += Wc[(size_t)(i+0)*c.N] * c.ubuf[i+0];
        a1 += Wc[(size_t)(i+1)*c.N] * c.ubuf[i+1];
        a2 += Wc[(size_t)(i+2)*c.N] * c.ubuf[i+2];
        a3 += Wc[(size_t)(i+3)*c.N] * c.ubuf[i+3];
        a4 += Wc[(size_t)(i+4)*c.N] * c.ubuf[i+4];
        a5 += Wc[(size_t)(i+5)*c.N] * c.ubuf[i+5];
        a6 += Wc[(size_t)(i+6)*c.N] * c.ubuf[i+6];
        a7 += Wc[(size_t)(i+7)*c.N] * c.ubuf[i+7];
    }
    for (; i < iend; ++i) a0 += Wc[(size_t)i*c.N] * c.ubuf[i];
    float acc = ((a0+a1)+(a2+a3)) + ((a4+a5)+(a6+a7));

    red[threadIdx.x] = acc;
    __syncthreads();
    if (seg == 0) {
        float tot = 0.0f;
        for (int s = 0; s < 8; ++s) tot += red[cl + s * 32];
        float yv = tot * su;
        c.ybuf[col] = yv;
        ssq[cl] = yv * yv;
    }
    __syncthreads();
    if (threadIdx.x == 0) {
        float p = 0.0f;
        for (int q = 0; q < 32; ++q) p += ssq[q];
        g_partY[c.m][c.bg] = p;
    }
    __syncthreads();
}

__device__ void phaseZ_unit(int u, const float* Win, const float* Wrec, const float* Wout,
                            float* red, float* wsq) {
    PiCtx c = pi_ctxZ(u, Win, Wrec, Wout);
    int gy = (c.m == 1) ? GY_REC : ((c.m == 0) ? GY_IN : GY_OUT);
    float ss = block_sum_partials(g_partY[c.m], gy, red);
    float sv = 1.0f / (sqrtf(ss) + EPSN);

    int warp = threadIdx.x >> 5, lane = threadIdx.x & 31;
    int rpb = (c.M + c.G - 1) / c.G;
    int rend = min(c.bg * rpb + rpb, c.M);

    float acc2 = 0.0f;
    for (int r = c.bg * rpb + warp; r < rend; r += 8) {
        const float* row = c.W + (size_t)r * c.N;
        float a0=0.f,a1=0.f,a2=0.f,a3=0.f,a4=0.f,a5=0.f,a6=0.f,a7=0.f;
        for (int j = lane; j < c.N; j += 256) {
            a0 += row[j      ] * c.ybuf[j      ];
            a1 += row[j +  32] * c.ybuf[j +  32];
            a2 += row[j +  64] * c.ybuf[j +  64];
            a3 += row[j +  96] * c.ybuf[j +  96];
            a4 += row[j + 128] * c.ybuf[j + 128];
            a5 += row[j + 160] * c.ybuf[j + 160];
            a6 += row[j + 192] * c.ybuf[j + 192];
            a7 += row[j + 224] * c.ybuf[j + 224];
        }
        float a = ((a0+a1)+(a2+a3)) + ((a4+a5)+(a6+a7));
        for (int o = 16; o; o >>= 1) a += __shfl_down_sync(0xffffffffu, a, o);
        if (lane == 0) {
            float z = a * sv;
            c.ubuf[r] = z;
            acc2 += z * z;
        }
    }
    if (lane == 0) wsq[warp] = acc2;
    __syncthreads();
    if (threadIdx.x == 0) {
        float p = 0.0f;
        for (int w = 0; w < 8; ++w) p += wsq[w];
        g_partZ[c.m][c.bg] = p;
    }
    __syncthreads();
}

__device__ void sigma_unit(int u, const float* Win, const float* Wrec, const float* Wout,
                           float* red, float* wsq) {
    PiCtx c = pi_ctxZ(u, Win, Wrec, Wout);
    int gy = (c.m == 1) ? GY_REC : ((c.m == 0) ? GY_IN : GY_OUT);
    float ssz = block_sum_partials(g_partZ[c.m], c.G, red);
    float ssy = block_sum_partials(g_partY[c.m], gy, red);
    float su = 1.0f / (sqrtf(ssz) + EPSN);
    float sv = 1.0f / (sqrtf(ssy) + EPSN);

    int warp = threadIdx.x >> 5, lane = threadIdx.x & 31;
    int rpb = (c.M + c.G - 1) / c.G;
    int rend = min(c.bg * rpb + rpb, c.M);

    float contrib = 0.0f;
    for (int r = c.bg * rpb + warp; r < rend; r += 8) {
        const float* row = c.W + (size_t)r * c.N;
        float a0=0.f,a1=0.f,a2=0.f,a3=0.f,a4=0.f,a5=0.f,a6=0.f,a7=0.f;
        for (int j = lane; j < c.N; j += 256) {
            a0 += row[j      ] * c.ybuf[j      ];
            a1 += row[j +  32] * c.ybuf[j +  32];
            a2 += row[j +  64] * c.ybuf[j +  64];
            a3 += row[j +  96] * c.ybuf[j +  96];
            a4 += row[j + 128] * c.ybuf[j + 128];
            a5 += row[j + 160] * c.ybuf[j + 160];
            a6 += row[j + 192] * c.ybuf[j + 192];
            a7 += row[j + 224] * c.ybuf[j + 224];
        }
        float a = ((a0+a1)+(a2+a3)) + ((a4+a5)+(a6+a7));
        for (int o = 16; o; o >>= 1) a += __shfl_down_sync(0xffffffffu, a, o);
        if (lane == 0) contrib += (su * c.ubuf[r]) * (sv * a);
    }
    if (lane == 0) wsq[warp] = contrib;
    __syncthreads();
    if (threadIdx.x == 0) {
        float p = 0.0f;
        for (int w = 0; w < 8; ++w) p += wsq[w];
        g_sigpart[c.m][c.bg] = p;
    }
    __syncthreads();
}

// Grid barrier: release-arrive (fence + atomicAdd), acquire-spin. All 296
// blocks co-resident by construction -> cannot deadlock.
__device__ __forceinline__ void grid_barrier(unsigned target) {
    __syncthreads();
    if (threadIdx.x == 0) {
        __threadfence();
        atomicAdd(&g_bar, 1u);
        unsigned v;
        do {
            asm volatile("ld.acquire.gpu.u32 %0, [%1];" : "=r"(v) : "l"(&g_bar) : "memory");
        } while (v < target);
    }
    __syncthreads();
}

__global__ __launch_bounds__(256, 2)
void pi_fused(const float* __restrict__ Win, const float* __restrict__ Wrec,
              const float* __restrict__ Wout) {
    __shared__ float red[256];
    __shared__ float ssq[32];
    __shared__ float wsq[8];
    unsigned nb = 0;
    for (int it = 0; it < NPI; ++it) {
        for (int u = blockIdx.x; u < NBY; u += NB_F)
            phaseY_unit(u, Win, Wrec, Wout, red, ssq);
        grid_barrier(++nb * NB_F);
        for (int u = blockIdx.x; u < NBZ; u += NB_F)
            phaseZ_unit(u, Win, Wrec, Wout, red, wsq);
        grid_barrier(++nb * NB_F);
    }
    for (int u = blockIdx.x; u < NBY; u += NB_F)      // final v = norm(W^T u)
        phaseY_unit(u, Win, Wrec, Wout, red, ssq);
    grid_barrier(++nb * NB_F);
    for (int u = blockIdx.x; u < NBZ; u += NB_F)      // sigma partials
        sigma_unit(u, Win, Wrec, Wout, red, wsq);
    grid_barrier(++nb * NB_F);
    if (blockIdx.x == 0 && threadIdx.x < 3) {
        int m = threadIdx.x;
        int G = (m == 1) ? GZ_REC : ((m == 0) ? GZ_IN : GZ_OUT);
        float s = 0.0f;
        for (int g = 0; g < G; ++g) s += g_sigpart[m][g];
        g_inv_sigma[m] = 1.0f / s;
    }
}

// ---------------------------------------------------------------------------
// MMA wrappers
// ---------------------------------------------------------------------------
__device__ __forceinline__ void mma_bf(float* c, uint32_t a0, uint32_t a1, uint32_t a2,
                                       uint32_t a3, uint32_t b0, uint32_t b1) {
    asm volatile(
        "mma.sync.aligned.m16n8k16.row.col.f32.bf16.bf16.f32 "
        "{%0,%1,%2,%3}, {%4,%5,%6,%7}, {%8,%9}, {%0,%1,%2,%3};"
        : "+f"(c[0]), "+f"(c[1]), "+f"(c[2]), "+f"(c[3])
        : "r"(a0), "r"(a1), "r"(a2), "r"(a3), "r"(b0), "r"(b1));
}
__device__ __forceinline__ void mma_hf(float* c, uint32_t a0, uint32_t a1, uint32_t a2,
                                       uint32_t a3, uint32_t b0, uint32_t b1) {
    asm volatile(
        "mma.sync.aligned.m16n8k16.row.col.f32.f16.f16.f32 "
        "{%0,%1,%2,%3}, {%4,%5,%6,%7}, {%8,%9}, {%0,%1,%2,%3};"
        : "+f"(c[0]), "+f"(c[1]), "+f"(c[2]), "+f"(c[3])
        : "r"(a0), "r"(a1), "r"(a2), "r"(a3), "r"(b0), "r"(b1));
}

#define BM 128
#define BN 128
#define BKT 32
#define PSTRIDE 20     // uint2 per packed-pair row (160B)
#define ASTRIDE 80     // bytes per fp16 A row (64 data + 16 pad)
#define A_ST_BYTES 10240
#define B_ST_BYTES 20480
#define H2_SMEM (2 * A_ST_BYTES + 2 * B_ST_BYTES)   // 61440

// ---------------------------------------------------------------------------
// 3-term bf16 GEMM on packed pairs (xproj only)
// ---------------------------------------------------------------------------
__global__ __launch_bounds__(256)
void gemm_bf3(const uint2* __restrict__ A, const uint2* __restrict__ B,
              float* __restrict__ Cf, int N, int K) {
    __shared__ __align__(16) uint2 As[BM * PSTRIDE];
    __shared__ __align__(16) uint2 Bs[BN * PSTRIDE];

    int tid = threadIdx.x;
    int bm = blockIdx.y * BM, bn = blockIdx.x * BN;
    int Kp = K >> 1;

    int rowq[4], uq[4];
#pragma unroll
    for (int q = 0; q < 4; ++q) {
        int idx = tid + q * 256;
        rowq[q] = idx >> 3;
        uq[q] = (idx & 7) * 2;
    }

    int warp = tid >> 5, lane = tid & 31;
    int wm = (warp & 1) * 64;
    int wn = (warp >> 1) * 32;
    int g = lane >> 2;
    int t = lane & 3;

    float acc[4][4][4];
#pragma unroll
    for (int i = 0; i < 4; ++i)
#pragma unroll
        for (int j = 0; j < 4; ++j)
#pragma unroll
            for (int q = 0; q < 4; ++q) acc[i][j][q] = 0.0f;

    uint4 pa[4], pb[4];
#pragma unroll
    for (int q = 0; q < 4; ++q) {
        pa[q] = *(const uint4*)(A + (size_t)(bm + rowq[q]) * Kp + uq[q]);
        pb[q] = *(const uint4*)(B + (size_t)(bn + rowq[q]) * Kp + uq[q]);
    }

    int KT = K / BKT;
    for (int kt = 0; kt < KT; ++kt) {
        __syncthreads();
#pragma unroll
        for (int q = 0; q < 4; ++q) {
            *(uint4*)&As[rowq[q] * PSTRIDE + uq[q]] = pa[q];
            *(uint4*)&Bs[rowq[q] * PSTRIDE + uq[q]] = pb[q];
        }
        __syncthreads();

        if (kt + 1 < KT) {
            int off = (kt + 1) * 16;
#pragma unroll
            for (int q = 0; q < 4; ++q) {
                pa[q] = *(const uint4*)(A + (size_t)(bm + rowq[q]) * Kp + off + uq[q]);
                pb[q] = *(const uint4*)(B + (size_t)(bn + rowq[q]) * Kp + off + uq[q]);
            }
        }

#pragma unroll
        for (int kp = 0; kp < 16; kp += 8) {
            uint2 Af[4][4];
            uint2 Bf[4][2];
#pragma unroll
            for (int mf = 0; mf < 4; ++mf) {
                int rb = wm + mf * 16 + g;
                Af[mf][0] = As[rb * PSTRIDE + kp + t];
                Af[mf][1] = As[(rb + 8) * PSTRIDE + kp + t];
                Af[mf][2] = As[rb * PSTRIDE + kp + t + 4];
                Af[mf][3] = As[(rb + 8) * PSTRIDE + kp + t + 4];
            }
#pragma unroll
            for (int nf = 0; nf < 4; ++nf) {
                int cb = wn + nf * 8 + g;
                Bf[nf][0] = Bs[cb * PSTRIDE + kp + t];
                Bf[nf][1] = Bs[cb * PSTRIDE + kp + t + 4];
            }
#pragma unroll
            for (int nf = 0; nf < 4; ++nf)
#pragma unroll
                for (int mf = 0; mf < 4; ++mf)
                    mma_bf(acc[mf][nf], Af[mf][0].x, Af[mf][1].x, Af[mf][2].x, Af[mf][3].x,
                           Bf[nf][0].x, Bf[nf][1].x);
#pragma unroll
            for (int nf = 0; nf < 4; ++nf)
#pragma unroll
                for (int mf = 0; mf < 4; ++mf)
                    mma_bf(acc[mf][nf], Af[mf][0].x, Af[mf][1].x, Af[mf][2].x, Af[mf][3].x,
                           Bf[nf][0].y, Bf[nf][1].y);
#pragma unroll
            for (int nf = 0; nf < 4; ++nf)
#pragma unroll
                for (int mf = 0; mf < 4; ++mf)
                    mma_bf(acc[mf][nf], Af[mf][0].y, Af[mf][1].y, Af[mf][2].y, Af[mf][3].y,
                           Bf[nf][0].x, Bf[nf][1].x);
        }
    }

#pragma unroll
    for (int mf = 0; mf < 4; ++mf) {
        int r0 = bm + wm + mf * 16 + g;
#pragma unroll
        for (int nf = 0; nf < 4; ++nf) {
            int c0 = bn + wn + nf * 8 + 2 * t;
            float* a = acc[mf][nf];
#pragma unroll
            for (int half = 0; half < 2; ++half) {
                int rr = r0 + half * 8;
                float2 o; o.x = a[half * 2 + 0]; o.y = a[half * 2 + 1];
                *(float2*)(Cf + (size_t)rr * N + c0) = o;
            }
        }
    }
}

// ---------------------------------------------------------------------------
// 2-term fp16 GEMM with cp.async 2-stage pipeline, 2 CTAs/SM.
// ---------------------------------------------------------------------------
template <int OKIND>
__global__ __launch_bounds__(256, 2)
void gemm_h2(const uint32_t* __restrict__ Ah, const uint2* __restrict__ B,
             const float* __restrict__ bias, const float* __restrict__ bias2,
             const float* __restrict__ raw, float* __restrict__ Cf,
             uint32_t* __restrict__ Cp, int N, int Nreal, int K) {
    extern __shared__ __align__(16) uint8_t dynsmem[];
    uint32_t sbase = smem_u32(dynsmem);
    const uint32_t aoff[2] = { 0u, A_ST_BYTES };
    const uint32_t boff[2] = { 2u * A_ST_BYTES, 2u * A_ST_BYTES + B_ST_BYTES };

    int tid = threadIdx.x;
    int bm = blockIdx.y * BM, bn = blockIdx.x * BN;
    int K8 = K >> 3;
    int Kp = K >> 1;

    int arow[2], aq[2];
#pragma unroll
    for (int q = 0; q < 2; ++q) {
        int idx = tid + q * 256;
        arow[q] = idx >> 2;
        aq[q] = idx & 3;
    }
    int brow[4], buq[4];
#pragma unroll
    for (int q = 0; q < 4; ++q) {
        int idx = tid + q * 256;
        brow[q] = idx >> 3;
        buq[q] = (idx & 7) * 2;
    }

    const uint4* A4 = (const uint4*)Ah;

    auto issue_tile = [&](int kt, int s) {
#pragma unroll
        for (int q = 0; q < 2; ++q)
            CP16(sbase + aoff[s] + arow[q] * ASTRIDE + aq[q] * 16,
                 A4 + (size_t)(bm + arow[q]) * K8 + kt * 4 + aq[q]);
#pragma unroll
        for (int q = 0; q < 4; ++q)
            CP16(sbase + boff[s] + brow[q] * 160 + buq[q] * 8,
                 (const uint4*)(B + (size_t)(bn + brow[q]) * Kp + kt * 16 + buq[q]));
        CP_COMMIT();
    };

    int warp = tid >> 5, lane = tid & 31;
    int wm = (warp & 1) * 64;
    int wn = (warp >> 1) * 32;
    int g = lane >> 2;
    int t = lane & 3;

    float acc[4][4][4];
#pragma unroll
    for (int i = 0; i < 4; ++i)
#pragma unroll
        for (int j = 0; j < 4; ++j)
#pragma unroll
            for (int q = 0; q < 4; ++q) acc[i][j][q] = 0.0f;

    int KT = K / BKT;
    issue_tile(0, 0);
    issue_tile(1, 1);

    for (int kt = 0; kt < KT; ++kt) {
        int s = kt & 1;
        if (kt + 1 < KT) { CP_WAIT(1); } else { CP_WAIT(0); }
        __syncthreads();

        const uint8_t* AsB = dynsmem + aoff[s];
        const uint2* Bs = (const uint2*)(dynsmem + boff[s]);
#pragma unroll
        for (int kh = 0; kh < 2; ++kh) {
            uint32_t Af[4][4];
#pragma unroll
            for (int mf = 0; mf < 4; ++mf) {
                int rb = wm + mf * 16 + g;
                const uint8_t* base = AsB + rb * ASTRIDE + kh * 32 + t * 4;
                Af[mf][0] = *(const uint32_t*)(base);
                Af[mf][1] = *(const uint32_t*)(base + 8 * ASTRIDE);
                Af[mf][2] = *(const uint32_t*)(base + 16);
                Af[mf][3] = *(const uint32_t*)(base + 8 * ASTRIDE + 16);
            }
            uint2 Bf[4][2];
            int kp = kh * 8;
#pragma unroll
            for (int nf = 0; nf < 4; ++nf) {
                int cb = wn + nf * 8 + g;
                Bf[nf][0] = Bs[cb * PSTRIDE + kp + t];
                Bf[nf][1] = Bs[cb * PSTRIDE + kp + t + 4];
            }
#pragma unroll
            for (int nf = 0; nf < 4; ++nf)
#pragma unroll
                for (int mf = 0; mf < 4; ++mf)
                    mma_hf(acc[mf][nf], Af[mf][0], Af[mf][1], Af[mf][2], Af[mf][3],
                           Bf[nf][0].x, Bf[nf][1].x);
#pragma unroll
            for (int nf = 0; nf < 4; ++nf)
#pragma unroll
                for (int mf = 0; mf < 4; ++mf)
                    mma_hf(acc[mf][nf], Af[mf][0], Af[mf][1], Af[mf][2], Af[mf][3],
                           Bf[nf][0].y, Bf[nf][1].y);
        }
        __syncthreads();
        if (kt + 2 < KT) issue_tile(kt + 2, s);
    }

    // ---- epilogue ----
    float s_main = (OKIND == 1) ? g_inv_sigma[1] : g_inv_sigma[2];
    float s_in = (OKIND == 1) ? g_inv_sigma[0] : 0.0f;
#pragma unroll
    for (int mf = 0; mf < 4; ++mf) {
        int r0 = bm + wm + mf * 16 + g;
#pragma unroll
        for (int nf = 0; nf < 4; ++nf) {
            int c0 = bn + wn + nf * 8 + 2 * t;
            float* a = acc[mf][nf];
#pragma unroll
            for (int half = 0; half < 2; ++half) {
                int rr = r0 + half * 8;
                float v0 = a[half * 2 + 0];
                float v1 = a[half * 2 + 1];
                if (OKIND == 1) {
                    size_t base = (size_t)rr * N + c0;
                    float2 rw = *(const float2*)(raw + base);
                    v0 = tanhf(v0 * s_main + bias[c0] + rw.x * s_in + bias2[c0]);
                    v1 = tanhf(v1 * s_main + bias[c0 + 1] + rw.y * s_in + bias2[c0 + 1]);
                    Cp[base >> 1] = pack_hf(v0, v1);
                } else {
                    size_t base = (size_t)rr * Nreal;
                    if (c0 < Nreal)     Cf[base + c0]     = v0 * s_main + bias[c0];
                    if (c0 + 1 < Nreal) Cf[base + c0 + 1] = v1 * s_main + bias[c0 + 1];
                }
            }
        }
    }
}

// Step 1 (h0 = 0): h = fp16( tanh(raw*s_in + b_in + b_rec) )
__global__ void step1_kernel(const float* __restrict__ xpraw, const float* __restrict__ bin,
                             const float* __restrict__ brec, uint32_t* __restrict__ hp) {
    size_t i = ((size_t)blockIdx.x * blockDim.x + threadIdx.x) * 4;
    float s_in = g_inv_sigma[0];
    float4 v = *(const float4*)(xpraw + i);
    int col = (int)(i & (HID - 1));
    v.x = tanhf(v.x * s_in + bin[col + 0] + brec[col + 0]);
    v.y = tanhf(v.y * s_in + bin[col + 1] + brec[col + 1]);
    v.z = tanhf(v.z * s_in + bin[col + 2] + brec[col + 2]);
    v.w = tanhf(v.w * s_in + bin[col + 3] + brec[col + 3]);
    uint2 o;
    o.x = pack_hf(v.x, v.y);
    o.y = pack_hf(v.z, v.w);
    *(uint2*)(hp + (i >> 1)) = o;
}

// ---------------------------------------------------------------------------
// Launch
// ---------------------------------------------------------------------------
extern "C" void kernel_launch(void* const* d_in, const int* in_sizes, int n_in,
                              void* d_out, int out_size) {
    (void)in_sizes; (void)n_in; (void)out_size;
    const float* x    = (const float*)d_in[0];
    const float* Win  = (const float*)d_in[1];
    const float* bin  = (const float*)d_in[2];
    const float* Wrec = (const float*)d_in[3];
    const float* brec = (const float*)d_in[4];
    const float* Wout = (const float*)d_in[5];
    const float* bout = (const float*)d_in[6];
    float* out = (float*)d_out;

    uint2 *xp, *winp, *wrecp, *woutp;
    uint32_t *hf0, *hf1;
    float* xraw;
    cudaGetSymbolAddress((void**)&xp, g_xp);
    cudaGetSymbolAddress((void**)&winp, g_Winp);
    cudaGetSymbolAddress((void**)&wrecp, g_Wrecp);
    cudaGetSymbolAddress((void**)&woutp, g_Woutp);
    cudaGetSymbolAddress((void**)&xraw, g_xraw);
    cudaGetSymbolAddress((void**)&hf0, g_hf0);
    cudaGetSymbolAddress((void**)&hf1, g_hf1);

    cudaFuncSetAttribute(gemm_h2<1>, cudaFuncAttributeMaxDynamicSharedMemorySize, H2_SMEM);
    cudaFuncSetAttribute(gemm_h2<2>, cudaFuncAttributeMaxDynamicSharedMemorySize, H2_SMEM);

    pi_init<<<1, 256>>>();
    prepack_bf<<<(BATCH * IN_DIM / 4) / 256, 256>>>(x, xp, BATCH * IN_DIM / 4);
    prepack_bf<<<(HID * IN_DIM / 4) / 256, 256>>>(Win, winp, HID * IN_DIM / 4);
    prepack_hf<<<(HID * HID / 4) / 256, 256>>>(Wrec, wrecp, HID * HID / 4);
    prepack_hf_pad<<<(NPAD_OUT * HID / 4) / 256, 256>>>(Wout, woutp, OUT_DIM, HID / 4,
                                                        NPAD_OUT * HID / 4);
    // raw xproj GEMM (3-term bf16, sigma-independent)
    gemm_bf3<<<dim3(HID / BN, BATCH / BM), 256>>>(xp, winp, xraw, HID, IN_DIM);

    // fused power iteration: 296 co-resident blocks (2/SM), 1 launch
    pi_fused<<<NB_F, 256>>>(Win, Wrec, Wout);

    // step 1
    step1_kernel<<<(BATCH * HID) / (256 * 4), 256>>>(xraw, bin, brec, hf0);

    // steps 2..30 (2-term fp16, cp.async pipeline)
    uint32_t* hin = hf0;
    uint32_t* hout = hf1;
    for (int s = 1; s < STEPS; ++s) {
        gemm_h2<1><<<dim3(HID / BN, BATCH / BM), 256, H2_SMEM>>>(
            hin, wrecp, brec, bin, xraw, nullptr, hout, HID, HID, HID);
        uint32_t* tmp = hin; hin = hout; hout = tmp;
    }

    // out GEMM
    gemm_h2<2><<<dim3(NPAD_OUT / BN, BATCH / BM), 256, H2_SMEM>>>(
        hin, woutp, bout, nullptr, nullptr, out, nullptr, NPAD_OUT, OUT_DIM, HID);
}